// round 15
// baseline (speedup 1.0000x reference)
#include <cuda_runtime.h>
#include <math.h>

#define NN 10000
#define NE 160000
#define FD 128
#define NRBF 20
#define PI_F 3.14159265358979f

// ---------------- device scratch (static, no runtime alloc) ----------------
__device__ float g_Sbar[NN*FD];
__device__ float g_V[NN*FD*3];
__device__ float g_Valt[NN*FD*3];
__device__ float g_Vb0[NN*FD*3];
__device__ float g_Vb1[NN*FD*3];
__device__ float g_phi[NN*640];
__device__ float g_tmp[NN*256];
__device__ float g_t2[NN*FD];
__device__ float g_a[NN*384];
__device__ float g_uv[NN*FD*3];
__device__ float g_vv[NN*FD*3];
__device__ float g_vn[NN*FD];
__device__ float g_unit[NE*3];
__device__ float g_env[NE];
__device__ float g_rbf[NE*NRBF];
__device__ int   g_cnt[NN];
__device__ int   g_off[NN+1];
__device__ int   g_cur[NN];
__device__ int   g_perm[NE];

// ---------------- CSR build ----------------
__global__ void count_kernel(const int* __restrict__ nbr) {
    int e = blockIdx.x*blockDim.x + threadIdx.x;
    if (e < NE) atomicAdd(&g_cnt[nbr[2*e]], 1);
}

__global__ void scan_kernel() {
    __shared__ int s[1024];
    int t = threadIdx.x;
    const int CH = (NN + 1023) / 1024;
    int base = t*CH;
    int local[CH];
    int sum = 0;
#pragma unroll
    for (int i = 0; i < CH; i++) {
        int v = (base+i < NN) ? g_cnt[base+i] : 0;
        local[i] = v; sum += v;
    }
    s[t] = sum;
    __syncthreads();
    for (int d = 1; d < 1024; d <<= 1) {
        int v = (t >= d) ? s[t-d] : 0;
        __syncthreads();
        s[t] += v;
        __syncthreads();
    }
    int prefix = (t == 0) ? 0 : s[t-1];
#pragma unroll
    for (int i = 0; i < CH; i++) {
        if (base+i < NN) {
            g_off[base+i] = prefix;
            g_cur[base+i] = prefix;
            prefix += local[i];
        }
    }
    if (t == 1023) g_off[NN] = s[1023];
}

__global__ void fill_kernel(const int* __restrict__ nbr) {
    int e = blockIdx.x*blockDim.x + threadIdx.x;
    if (e < NE) {
        int sN = nbr[2*e];
        int p = atomicAdd(&g_cur[sN], 1);
        g_perm[p] = e;
    }
}

__global__ void sort_kernel() {
    int i = blockIdx.x*blockDim.x + threadIdx.x;
    if (i >= NN) return;
    int a = g_off[i], b = g_off[i+1];
    for (int x = a+1; x < b; x++) {
        int v = g_perm[x];
        int y = x-1;
        while (y >= a && g_perm[y] > v) { g_perm[y+1] = g_perm[y]; y--; }
        g_perm[y+1] = v;
    }
}

// ---------------- edge geometry ----------------
__global__ void edge_geom_kernel(const float* __restrict__ xyz,
                                 const int* __restrict__ nbr) {
    int e = blockIdx.x*blockDim.x + threadIdx.x;
    if (e >= NE) return;
    int s = nbr[2*e], d = nbr[2*e+1];
    float dx = xyz[3*d+0] - xyz[3*s+0];
    float dy = xyz[3*d+1] - xyz[3*s+1];
    float dz = xyz[3*d+2] - xyz[3*s+2];
    float dist = sqrtf(dx*dx + dy*dy + dz*dz);
    float inv = 1.0f / dist;
    g_unit[3*e+0] = dx*inv;
    g_unit[3*e+1] = dy*inv;
    g_unit[3*e+2] = dz*inv;
    g_env[e] = (dist < 5.0f) ? 0.5f*(__cosf(PI_F*dist*0.2f) + 1.0f) : 0.0f;
    float base = PI_F*0.2f*dist;
#pragma unroll
    for (int k = 0; k < NRBF; k++)
        g_rbf[e*NRBF+k] = __sinf((float)(k+1)*base) * inv;
}

// ---------------- general fused GEMM (BK templated) ----------------
// C[M,N] = act(A @ W + b). A logical [M,K]: cols [0,K0) from A0, rest from A1.
template<int BM, int BN, int TM, int TN, int BK, int OCC, int ACT>
__global__ void __launch_bounds__((BM/TM)*(BN/TN), OCC) gemm_tc(
    const float* __restrict__ A0, int lda0,
    const float* __restrict__ A1, int lda1, int K0,
    const float* __restrict__ W, const float* __restrict__ bias,
    float* __restrict__ C, int M, int N, int K)
{
    const int NT  = (BM/TM)*(BN/TN);
    const int ASL = BM*(BK/4)/NT;
    const int BSL = BN*(BK/4)/NT;
    static_assert(ASL >= 1 && BSL >= 1, "tile/thread mismatch");
    __shared__ __align__(16) float As[2][BK][BM];
    __shared__ __align__(16) float Bs[2][BK][BN];

    int t  = threadIdx.x;
    int bm = blockIdx.y*BM, bn = blockIdx.x*BN;
    int tx = t % (BN/TN);
    int ty = t / (BN/TN);

    float acc[TM][TN];
#pragma unroll
    for (int i = 0; i < TM; i++)
#pragma unroll
        for (int j = 0; j < TN; j++) acc[i][j] = 0.0f;

    float4 ra[ASL];
    float4 rb[BSL];

#define LOAD_AB(k0)                                                           \
    {   _Pragma("unroll")                                                     \
        for (int i = 0; i < ASL; i++) {                                       \
            int idx = t + i*NT;                                               \
            int am = idx % BM, kc = idx / BM;                                 \
            int gm = bm + am, gk = (k0) + kc*4;                               \
            if (gm < M) {                                                     \
                const float* p = (gk < K0) ? (A0 + (size_t)gm*lda0 + gk)      \
                                           : (A1 + (size_t)gm*lda1 + (gk-K0));\
                ra[i] = *(const float4*)p;                                    \
            } else ra[i] = make_float4(0,0,0,0);                              \
        }                                                                     \
        _Pragma("unroll")                                                     \
        for (int i = 0; i < BSL; i++) {                                       \
            int idx = t + i*NT;                                               \
            int n4 = (idx % (BN/4))*4, k = idx / (BN/4);                      \
            rb[i] = *(const float4*)(W + (size_t)((k0)+k)*N + bn + n4);       \
        }                                                                     \
    }
#define STORE_AB(st)                                                          \
    {   _Pragma("unroll")                                                     \
        for (int i = 0; i < ASL; i++) {                                       \
            int idx = t + i*NT;                                               \
            int am = idx % BM, kc = idx / BM;                                 \
            As[st][kc*4+0][am] = ra[i].x;                                     \
            As[st][kc*4+1][am] = ra[i].y;                                     \
            As[st][kc*4+2][am] = ra[i].z;                                     \
            As[st][kc*4+3][am] = ra[i].w;                                     \
        }                                                                     \
        _Pragma("unroll")                                                     \
        for (int i = 0; i < BSL; i++) {                                       \
            int idx = t + i*NT;                                               \
            int n4 = (idx % (BN/4))*4, k = idx / (BN/4);                      \
            *(float4*)&Bs[st][k][n4] = rb[i];                                 \
        }                                                                     \
    }
#define COMPUTE(st)                                                           \
    {   _Pragma("unroll")                                                     \
        for (int kk = 0; kk < BK; kk++) {                                     \
            float av[TM], bv[TN];                                             \
            _Pragma("unroll")                                                 \
            for (int i = 0; i < TM; i += 4)                                   \
                *(float4*)&av[i] = *(const float4*)&As[st][kk][ty*TM + i];    \
            _Pragma("unroll")                                                 \
            for (int j = 0; j < TN; j += 4)                                   \
                *(float4*)&bv[j] = *(const float4*)&Bs[st][kk][tx*TN + j];    \
            _Pragma("unroll")                                                 \
            for (int i = 0; i < TM; i++)                                      \
            _Pragma("unroll")                                                 \
            for (int j = 0; j < TN; j++)                                      \
                acc[i][j] = fmaf(av[i], bv[j], acc[i][j]);                    \
        }                                                                     \
    }

    LOAD_AB(0);
    STORE_AB(0);
    __syncthreads();

    int st = 0;
    for (int k0 = BK; k0 < K; k0 += BK) {
        LOAD_AB(k0);
        COMPUTE(st);
        STORE_AB(st^1);
        __syncthreads();
        st ^= 1;
    }
    COMPUTE(st);

    float bj[TN];
#pragma unroll
    for (int j = 0; j < TN; j += 4)
        *(float4*)&bj[j] = *(const float4*)(bias + bn + tx*TN + j);
#pragma unroll
    for (int i = 0; i < TM; i++) {
        int gm = bm + ty*TM + i;
        if (gm >= M) continue;
        float* cp = C + (size_t)gm*N + bn + tx*TN;
#pragma unroll
        for (int j = 0; j < TN; j += 4) {
            float4 v;
            v.x = acc[i][j+0] + bj[j+0];
            v.y = acc[i][j+1] + bj[j+1];
            v.z = acc[i][j+2] + bj[j+2];
            v.w = acc[i][j+3] + bj[j+3];
            if (ACT) {
                v.x = v.x / (1.0f + __expf(-v.x));
                v.y = v.y / (1.0f + __expf(-v.y));
                v.z = v.z / (1.0f + __expf(-v.z));
                v.w = v.w / (1.0f + __expf(-v.w));
            }
            *(float4*)(cp + j) = v;
        }
    }
#undef LOAD_AB
#undef STORE_AB
#undef COMPUTE
}

// ---------------- edge aggregation (exact R2-best version) ----------------
__global__ void __launch_bounds__(128, 3) agg_kernel(
    const float* __restrict__ phi, const float* __restrict__ dW,
    const float* __restrict__ db, const int* __restrict__ nbr,
    const float* __restrict__ Vin, float* __restrict__ Vout,
    const float* __restrict__ Vbin, float* __restrict__ Vbout,
    float* __restrict__ H, float* __restrict__ Sbar)
{
    const int f = threadIdx.x;
    float wreg[5][NRBF];
    float breg[5];
#pragma unroll
    for (int c = 0; c < 5; c++) {
        breg[c] = db[c*128 + f];
#pragma unroll
        for (int k = 0; k < NRBF; k++)
            wreg[c][k] = dW[k*640 + c*128 + f];
    }
    int i0 = blockIdx.x * 8;
    for (int ii = 0; ii < 8; ii++) {
        int i = i0 + ii;
        if (i >= NN) return;
        float aH = 0.f, aS = 0.f;
        float aV0 = 0.f, aV1 = 0.f, aV2 = 0.f;
        float aB0 = 0.f, aB1 = 0.f, aB2 = 0.f;
        int e0 = g_off[i], e1 = g_off[i+1];
        int e_n = 0, j_n = 0;
        if (e0 < e1) { e_n = g_perm[e0]; j_n = nbr[2*e_n+1]; }
        for (int p = e0; p < e1; p++) {
            int e = e_n, j = j_n;
            if (p+1 < e1) { e_n = g_perm[p+1]; j_n = nbr[2*e_n+1]; }
            float ev = g_env[e];
            float u0 = g_unit[3*e+0], u1 = g_unit[3*e+1], u2 = g_unit[3*e+2];
            const float4* rq = (const float4*)(g_rbf + e*NRBF);
            float4 q0 = rq[0], q1 = rq[1], q2 = rq[2], q3 = rq[3], q4 = rq[4];
            float r[NRBF] = {q0.x,q0.y,q0.z,q0.w, q1.x,q1.y,q1.z,q1.w,
                             q2.x,q2.y,q2.z,q2.w, q3.x,q3.y,q3.z,q3.w,
                             q4.x,q4.y,q4.z,q4.w};
            const float* pj = phi + (size_t)j*640 + f;
            float p0 = pj[0], p1 = pj[128], p2 = pj[256], p3 = pj[384], p4 = pj[512];
            const float* vj = Vin  + ((size_t)j*128 + f)*3;
            const float* bjv = Vbin + ((size_t)j*128 + f)*3;
            float v0 = vj[0], v1 = vj[1], v2 = vj[2];
            float b0 = bjv[0], b1 = bjv[1], b2 = bjv[2];
            float w[5];
#pragma unroll
            for (int c = 0; c < 5; c++) {
                float s = breg[c];
#pragma unroll
                for (int k = 0; k < NRBF; k++)
                    s = fmaf(r[k], wreg[c][k], s);
                w[c] = s * ev;
            }
            float i0v = p0 * w[0];
            float i1v = p1 * w[1];
            float i2v = p2 * w[2];
            float i3v = p3 * w[3];
            float i4v = p4 * w[4];
            aH += i1v;
            aS += i3v;
            float ua0 = i2v*u0, ua1 = i2v*u1, ua2 = i2v*u2;
            aV0 += ua0 + i0v*v0;
            aV1 += ua1 + i0v*v1;
            aV2 += ua2 + i0v*v2;
            aB0 += ua0 + i4v*b0;
            aB1 += ua1 + i4v*b1;
            aB2 += ua2 + i4v*b2;
        }
        size_t hi = (size_t)i*128 + f;
        H[hi]    += aH;
        Sbar[hi] += aS;
        size_t vi = hi*3;
        Vout[vi+0]  = Vin[vi+0]  + aV0;
        Vout[vi+1]  = Vin[vi+1]  + aV1;
        Vout[vi+2]  = Vin[vi+2]  + aV2;
        Vbout[vi+0] = Vbin[vi+0] + aB0;
        Vbout[vi+1] = Vbin[vi+1] + aB1;
        Vbout[vi+2] = Vbin[vi+2] + aB2;
    }
}

// ---------------- u_v / v_v / v_norm (8 nodes/block, [d][f] smem, float4 LDS) --
__global__ void __launch_bounds__(128) upd_uv_kernel(
    const float* __restrict__ Vc, const float* __restrict__ U,
    const float* __restrict__ Wt,
    float* __restrict__ uv, float* __restrict__ vv, float* __restrict__ vn)
{
    __shared__ __align__(16) float sV[8][3][128];   // 12 KB
    int g = threadIdx.x;
    int n0 = blockIdx.x * 8;
#pragma unroll
    for (int n = 0; n < 8; n++) {
        const float* src = Vc + (size_t)(n0+n)*384;
#pragma unroll
        for (int r = 0; r < 3; r++) {
            int j = r*128 + g;          // j = f*3 + d
            sV[n][j % 3][j / 3] = src[j];
        }
    }
    __syncthreads();
    float aU[8][3] = {}, aV[8][3] = {};
    for (int f = 0; f < 128; f += 4) {
        float u0 = U[(f+0)*128 + g], u1 = U[(f+1)*128 + g];
        float u2 = U[(f+2)*128 + g], u3 = U[(f+3)*128 + g];
        float w0 = Wt[(f+0)*128 + g], w1 = Wt[(f+1)*128 + g];
        float w2 = Wt[(f+2)*128 + g], w3 = Wt[(f+3)*128 + g];
#pragma unroll
        for (int n = 0; n < 8; n++) {
#pragma unroll
            for (int d = 0; d < 3; d++) {
                float4 x = *(const float4*)&sV[n][d][f];
                float su = aU[n][d];
                su = fmaf(u0, x.x, su);
                su = fmaf(u1, x.y, su);
                su = fmaf(u2, x.z, su);
                su = fmaf(u3, x.w, su);
                aU[n][d] = su;
                float sw = aV[n][d];
                sw = fmaf(w0, x.x, sw);
                sw = fmaf(w1, x.y, sw);
                sw = fmaf(w2, x.z, sw);
                sw = fmaf(w3, x.w, sw);
                aV[n][d] = sw;
            }
        }
    }
#pragma unroll
    for (int n = 0; n < 8; n++) {
        int node = n0 + n;
        float nv = sqrtf(aV[n][0]*aV[n][0] + aV[n][1]*aV[n][1] +
                         aV[n][2]*aV[n][2] + 1e-15f);
        vn[(size_t)node*128 + g] = nv;
        size_t b = ((size_t)node*128 + g)*3;
        uv[b+0] = aU[n][0]; uv[b+1] = aU[n][1]; uv[b+2] = aU[n][2];
        vv[b+0] = aV[n][0]; vv[b+1] = aV[n][1]; vv[b+2] = aV[n][2];
    }
}

// ---------------- final gated update ----------------
__global__ void final_upd_kernel(float* __restrict__ H, float* __restrict__ V,
                                 const float* __restrict__ uv,
                                 const float* __restrict__ vv,
                                 const float* __restrict__ a)
{
    int idx = blockIdx.x*blockDim.x + threadIdx.x;
    if (idx >= NN*128) return;
    int n = idx >> 7, g = idx & 127;
    float a0 = a[(size_t)n*384 + g];
    float a1 = a[(size_t)n*384 + 128 + g];
    float a2 = a[(size_t)n*384 + 256 + g];
    size_t b = (size_t)idx*3;
    float u0 = uv[b], u1 = uv[b+1], u2 = uv[b+2];
    float dot = u0*vv[b] + u1*vv[b+1] + u2*vv[b+2];
    H[idx] += fmaf(a1, dot, a2);
    V[b+0] += a0*u0;
    V[b+1] += a0*u1;
    V[b+2] += a0*u2;
}

// ---------------- host ----------------
extern "C" void kernel_launch(void* const* d_in, const int* in_sizes, int n_in,
                              void* d_out, int out_size) {
    const float* xyz    = (const float*)d_in[0];
    const int*   nbr    = (const int*)  d_in[1];
    const float* Hin    = (const float*)d_in[3];
    const float* msg_W1 = (const float*)d_in[4];
    const float* msg_b1 = (const float*)d_in[5];
    const float* msg_W2 = (const float*)d_in[6];
    const float* msg_b2 = (const float*)d_in[7];
    const float* dist_W = (const float*)d_in[8];
    const float* dist_b = (const float*)d_in[9];
    const float* upd_U  = (const float*)d_in[10];
    const float* upd_Vw = (const float*)d_in[11];
    const float* upd_W1 = (const float*)d_in[12];
    const float* upd_b1 = (const float*)d_in[13];
    const float* upd_W2 = (const float*)d_in[14];
    const float* upd_b2 = (const float*)d_in[15];

    float* outH = (float*)d_out;

    float *Sbar, *V, *Valt, *Vb0, *Vb1, *phi, *tmp, *t2, *aBuf, *uv, *vv, *vn;
    int* cnt;
    cudaGetSymbolAddress((void**)&Sbar, g_Sbar);
    cudaGetSymbolAddress((void**)&V,    g_V);
    cudaGetSymbolAddress((void**)&Valt, g_Valt);
    cudaGetSymbolAddress((void**)&Vb0,  g_Vb0);
    cudaGetSymbolAddress((void**)&Vb1,  g_Vb1);
    cudaGetSymbolAddress((void**)&phi,  g_phi);
    cudaGetSymbolAddress((void**)&tmp,  g_tmp);
    cudaGetSymbolAddress((void**)&t2,   g_t2);
    cudaGetSymbolAddress((void**)&aBuf, g_a);
    cudaGetSymbolAddress((void**)&uv,   g_uv);
    cudaGetSymbolAddress((void**)&vv,   g_vv);
    cudaGetSymbolAddress((void**)&vn,   g_vn);
    cudaGetSymbolAddress((void**)&cnt,  g_cnt);

    float* outV = (out_size >= NN*FD + NN*FD*3) ? (outH + NN*FD) : Valt;

    // init via DMA (graph-capturable async memops)
    cudaMemsetAsync(cnt,  0, NN*sizeof(int));
    cudaMemsetAsync(Sbar, 0, (size_t)NN*FD*sizeof(float));
    cudaMemsetAsync(V,    0, (size_t)NN*FD*3*sizeof(float));
    cudaMemsetAsync(Vb0,  0, (size_t)NN*FD*3*sizeof(float));
    cudaMemcpyAsync(outH, Hin, (size_t)NN*FD*sizeof(float),
                    cudaMemcpyDeviceToDevice);

    count_kernel<<<(NE+255)/256, 256>>>(nbr);
    scan_kernel<<<1, 1024>>>();

    float* Vbufs[2] = {V,   outV};
    float* Bbufs[2] = {Vb0, Vb1};

    const int MT32 = (NN + 31) / 32;   // 313

    for (int l = 0; l < 3; l++) {
        const float* W1  = msg_W1 + (size_t)l*256*256;
        const float* b1  = msg_b1 + (size_t)l*256;
        const float* W2  = msg_W2 + (size_t)l*256*640;
        const float* b2  = msg_b2 + (size_t)l*640;
        const float* dWl = dist_W + (size_t)l*20*640;
        const float* dbl = dist_b + (size_t)l*640;
        const float* Ul  = upd_U  + (size_t)l*128*128;
        const float* Wtl = upd_Vw + (size_t)l*128*128;
        const float* uW1 = upd_W1 + (size_t)l*256*128;
        const float* ub1 = upd_b1 + (size_t)l*128;
        const float* uW2 = upd_W2 + (size_t)l*128*384;
        const float* ub2 = upd_b2 + (size_t)l*384;

        float* Vin   = Vbufs[l & 1];
        float* Vout_ = Vbufs[(l+1) & 1];
        float* Bin   = Bbufs[l & 1];
        float* Bout  = Bbufs[(l+1) & 1];

        // tmp = silu([H|Sbar] @ W1 + b1)   [10000,256]  grid=(4,313)
        gemm_tc<32,64,4,4,32,6,1><<<dim3(256/64, MT32), 128>>>(
            outH, 128, Sbar, 128, 128, W1, b1, tmp, NN, 256, 256);
        if (l == 0) {
            fill_kernel<<<(NE+255)/256, 256>>>(nbr);
            sort_kernel<<<(NN+127)/128, 128>>>();
            edge_geom_kernel<<<(NE+127)/128, 128>>>(xyz, nbr);
        }
        // phi = tmp @ W2 + b2              [10000,640]  grid=(10,313)
        gemm_tc<32,64,4,4,32,6,0><<<dim3(640/64, MT32), 128>>>(
            tmp, 256, tmp, 256, 256, W2, b2, phi, NN, 640, 256);
        // message aggregation
        agg_kernel<<<(NN+7)/8, 128>>>(phi, dWl, dbl, nbr,
                                      Vin, Vout_, Bin, Bout, outH, Sbar);
        // u_v, v_v, v_norm (8 nodes/block)
        upd_uv_kernel<<<NN/8, 128>>>(Vout_, Ul, Wtl, uv, vv, vn);
        // t2 = silu([H|v_norm] @ uW1 + ub1)  [10000,128]  grid=(2,313)
        gemm_tc<32,64,4,4,32,6,1><<<dim3(128/64, MT32), 128>>>(
            outH, 128, vn, 128, 128, uW1, ub1, t2, NN, 128, 256);
        // a = t2 @ uW2 + ub2               [10000,384]  grid=(6,313)
        gemm_tc<32,64,4,4,32,6,0><<<dim3(384/64, MT32), 128>>>(
            t2, 128, t2, 128, 128, uW2, ub2, aBuf, NN, 384, 128);
        // H += a1*dot + a2 ; V += a0*u_v
        final_upd_kernel<<<(NN*128+255)/256, 256>>>(outH, Vout_, uv, vv, aBuf);
    }
}

// round 16
// speedup vs baseline: 1.0299x; 1.0299x over previous
#include <cuda_runtime.h>
#include <math.h>

#define NN 10000
#define NE 160000
#define FD 128
#define NRBF 20
#define PI_F 3.14159265358979f

// ---------------- device scratch (static, no runtime alloc) ----------------
__device__ float g_Sbar[NN*FD];
__device__ float g_V[NN*FD*3];
__device__ float g_Valt[NN*FD*3];
__device__ float g_Vb0[NN*FD*3];
__device__ float g_Vb1[NN*FD*3];
__device__ float g_phi[NN*640];
__device__ float g_tmp[NN*256];
__device__ float g_t2[NN*FD];
__device__ float g_a[NN*384];
__device__ float g_uv[NN*FD*3];
__device__ float g_vv[NN*FD*3];
__device__ float g_vn[NN*FD];
__device__ float g_unit[NE*3];
__device__ float g_env[NE];
__device__ float g_rbf[NE*NRBF];
__device__ int   g_cnt[NN];
__device__ int   g_off[NN+1];
__device__ int   g_cur[NN];
__device__ int   g_perm[NE];

// ---------------- CSR build ----------------
__global__ void count_kernel(const int* __restrict__ nbr) {
    int e = blockIdx.x*blockDim.x + threadIdx.x;
    if (e < NE) atomicAdd(&g_cnt[nbr[2*e]], 1);
}

__global__ void scan_kernel() {
    __shared__ int s[1024];
    int t = threadIdx.x;
    const int CH = (NN + 1023) / 1024;
    int base = t*CH;
    int local[CH];
    int sum = 0;
#pragma unroll
    for (int i = 0; i < CH; i++) {
        int v = (base+i < NN) ? g_cnt[base+i] : 0;
        local[i] = v; sum += v;
    }
    s[t] = sum;
    __syncthreads();
    for (int d = 1; d < 1024; d <<= 1) {
        int v = (t >= d) ? s[t-d] : 0;
        __syncthreads();
        s[t] += v;
        __syncthreads();
    }
    int prefix = (t == 0) ? 0 : s[t-1];
#pragma unroll
    for (int i = 0; i < CH; i++) {
        if (base+i < NN) {
            g_off[base+i] = prefix;
            g_cur[base+i] = prefix;
            prefix += local[i];
        }
    }
    if (t == 1023) g_off[NN] = s[1023];
}

__global__ void fill_kernel(const int* __restrict__ nbr) {
    int e = blockIdx.x*blockDim.x + threadIdx.x;
    if (e < NE) {
        int sN = nbr[2*e];
        int p = atomicAdd(&g_cur[sN], 1);
        g_perm[p] = e;
    }
}

__global__ void sort_kernel() {
    int i = blockIdx.x*blockDim.x + threadIdx.x;
    if (i >= NN) return;
    int a = g_off[i], b = g_off[i+1];
    for (int x = a+1; x < b; x++) {
        int v = g_perm[x];
        int y = x-1;
        while (y >= a && g_perm[y] > v) { g_perm[y+1] = g_perm[y]; y--; }
        g_perm[y+1] = v;
    }
}

// ---------------- edge geometry ----------------
__global__ void edge_geom_kernel(const float* __restrict__ xyz,
                                 const int* __restrict__ nbr) {
    int e = blockIdx.x*blockDim.x + threadIdx.x;
    if (e >= NE) return;
    int s = nbr[2*e], d = nbr[2*e+1];
    float dx = xyz[3*d+0] - xyz[3*s+0];
    float dy = xyz[3*d+1] - xyz[3*s+1];
    float dz = xyz[3*d+2] - xyz[3*s+2];
    float dist = sqrtf(dx*dx + dy*dy + dz*dz);
    float inv = 1.0f / dist;
    g_unit[3*e+0] = dx*inv;
    g_unit[3*e+1] = dy*inv;
    g_unit[3*e+2] = dz*inv;
    g_env[e] = (dist < 5.0f) ? 0.5f*(__cosf(PI_F*dist*0.2f) + 1.0f) : 0.0f;
    float base = PI_F*0.2f*dist;
#pragma unroll
    for (int k = 0; k < NRBF; k++)
        g_rbf[e*NRBF+k] = __sinf((float)(k+1)*base) * inv;
}

// ---------------- general fused GEMM (R14 config, BK=16) ----------------
template<int BM, int BN, int TM, int TN, int OCC, int ACT>
__global__ void __launch_bounds__((BM/TM)*(BN/TN), OCC) gemm_tc(
    const float* __restrict__ A0, int lda0,
    const float* __restrict__ A1, int lda1, int K0,
    const float* __restrict__ W, const float* __restrict__ bias,
    float* __restrict__ C, int M, int N, int K)
{
    const int BK = 16;
    const int NT  = (BM/TM)*(BN/TN);
    const int ASL = BM*(BK/4)/NT;
    const int BSL = BN*(BK/4)/NT;
    static_assert(ASL >= 1 && BSL >= 1, "tile/thread mismatch");
    __shared__ __align__(16) float As[2][BK][BM];
    __shared__ __align__(16) float Bs[2][BK][BN];

    int t  = threadIdx.x;
    int bm = blockIdx.y*BM, bn = blockIdx.x*BN;
    int tx = t % (BN/TN);
    int ty = t / (BN/TN);

    float acc[TM][TN];
#pragma unroll
    for (int i = 0; i < TM; i++)
#pragma unroll
        for (int j = 0; j < TN; j++) acc[i][j] = 0.0f;

    float4 ra[ASL];
    float4 rb[BSL];

#define LOAD_AB(k0)                                                           \
    {   _Pragma("unroll")                                                     \
        for (int i = 0; i < ASL; i++) {                                       \
            int idx = t + i*NT;                                               \
            int am = idx % BM, kc = idx / BM;                                 \
            int gm = bm + am, gk = (k0) + kc*4;                               \
            if (gm < M) {                                                     \
                const float* p = (gk < K0) ? (A0 + (size_t)gm*lda0 + gk)      \
                                           : (A1 + (size_t)gm*lda1 + (gk-K0));\
                ra[i] = *(const float4*)p;                                    \
            } else ra[i] = make_float4(0,0,0,0);                              \
        }                                                                     \
        _Pragma("unroll")                                                     \
        for (int i = 0; i < BSL; i++) {                                       \
            int idx = t + i*NT;                                               \
            int n4 = (idx % (BN/4))*4, k = idx / (BN/4);                      \
            rb[i] = *(const float4*)(W + (size_t)((k0)+k)*N + bn + n4);       \
        }                                                                     \
    }
#define STORE_AB(st)                                                          \
    {   _Pragma("unroll")                                                     \
        for (int i = 0; i < ASL; i++) {                                       \
            int idx = t + i*NT;                                               \
            int am = idx % BM, kc = idx / BM;                                 \
            As[st][kc*4+0][am] = ra[i].x;                                     \
            As[st][kc*4+1][am] = ra[i].y;                                     \
            As[st][kc*4+2][am] = ra[i].z;                                     \
            As[st][kc*4+3][am] = ra[i].w;                                     \
        }                                                                     \
        _Pragma("unroll")                                                     \
        for (int i = 0; i < BSL; i++) {                                       \
            int idx = t + i*NT;                                               \
            int n4 = (idx % (BN/4))*4, k = idx / (BN/4);                      \
            *(float4*)&Bs[st][k][n4] = rb[i];                                 \
        }                                                                     \
    }
#define COMPUTE(st)                                                           \
    {   _Pragma("unroll")                                                     \
        for (int kk = 0; kk < BK; kk++) {                                     \
            float av[TM], bv[TN];                                             \
            _Pragma("unroll")                                                 \
            for (int i = 0; i < TM; i += 4)                                   \
                *(float4*)&av[i] = *(const float4*)&As[st][kk][ty*TM + i];    \
            _Pragma("unroll")                                                 \
            for (int j = 0; j < TN; j += 4)                                   \
                *(float4*)&bv[j] = *(const float4*)&Bs[st][kk][tx*TN + j];    \
            _Pragma("unroll")                                                 \
            for (int i = 0; i < TM; i++)                                      \
            _Pragma("unroll")                                                 \
            for (int j = 0; j < TN; j++)                                      \
                acc[i][j] = fmaf(av[i], bv[j], acc[i][j]);                    \
        }                                                                     \
    }

    LOAD_AB(0);
    STORE_AB(0);
    __syncthreads();

    int st = 0;
    for (int k0 = BK; k0 < K; k0 += BK) {
        LOAD_AB(k0);
        COMPUTE(st);
        STORE_AB(st^1);
        __syncthreads();
        st ^= 1;
    }
    COMPUTE(st);

    float bj[TN];
#pragma unroll
    for (int j = 0; j < TN; j += 4)
        *(float4*)&bj[j] = *(const float4*)(bias + bn + tx*TN + j);
#pragma unroll
    for (int i = 0; i < TM; i++) {
        int gm = bm + ty*TM + i;
        if (gm >= M) continue;
        float* cp = C + (size_t)gm*N + bn + tx*TN;
#pragma unroll
        for (int j = 0; j < TN; j += 4) {
            float4 v;
            v.x = acc[i][j+0] + bj[j+0];
            v.y = acc[i][j+1] + bj[j+1];
            v.z = acc[i][j+2] + bj[j+2];
            v.w = acc[i][j+3] + bj[j+3];
            if (ACT) {
                v.x = v.x / (1.0f + __expf(-v.x));
                v.y = v.y / (1.0f + __expf(-v.y));
                v.z = v.z / (1.0f + __expf(-v.z));
                v.w = v.w / (1.0f + __expf(-v.w));
            }
            *(float4*)(cp + j) = v;
        }
    }
#undef LOAD_AB
#undef STORE_AB
#undef COMPUTE
}

// ---------------- edge aggregation (R2 compute, 4 nodes/block) ----------------
__global__ void __launch_bounds__(128, 3) agg_kernel(
    const float* __restrict__ phi, const float* __restrict__ dW,
    const float* __restrict__ db, const int* __restrict__ nbr,
    const float* __restrict__ Vin, float* __restrict__ Vout,
    const float* __restrict__ Vbin, float* __restrict__ Vbout,
    float* __restrict__ H, float* __restrict__ Sbar)
{
    const int f = threadIdx.x;
    float wreg[5][NRBF];
    float breg[5];
#pragma unroll
    for (int c = 0; c < 5; c++) {
        breg[c] = db[c*128 + f];
#pragma unroll
        for (int k = 0; k < NRBF; k++)
            wreg[c][k] = dW[k*640 + c*128 + f];
    }
    int i0 = blockIdx.x * 4;
    for (int ii = 0; ii < 4; ii++) {
        int i = i0 + ii;
        if (i >= NN) return;
        float aH = 0.f, aS = 0.f;
        float aV0 = 0.f, aV1 = 0.f, aV2 = 0.f;
        float aB0 = 0.f, aB1 = 0.f, aB2 = 0.f;
        int e0 = g_off[i], e1 = g_off[i+1];
        int e_n = 0, j_n = 0;
        if (e0 < e1) { e_n = g_perm[e0]; j_n = nbr[2*e_n+1]; }
        for (int p = e0; p < e1; p++) {
            int e = e_n, j = j_n;
            if (p+1 < e1) { e_n = g_perm[p+1]; j_n = nbr[2*e_n+1]; }
            float ev = g_env[e];
            float u0 = g_unit[3*e+0], u1 = g_unit[3*e+1], u2 = g_unit[3*e+2];
            const float4* rq = (const float4*)(g_rbf + e*NRBF);
            float4 q0 = rq[0], q1 = rq[1], q2 = rq[2], q3 = rq[3], q4 = rq[4];
            float r[NRBF] = {q0.x,q0.y,q0.z,q0.w, q1.x,q1.y,q1.z,q1.w,
                             q2.x,q2.y,q2.z,q2.w, q3.x,q3.y,q3.z,q3.w,
                             q4.x,q4.y,q4.z,q4.w};
            const float* pj = phi + (size_t)j*640 + f;
            float p0 = pj[0], p1 = pj[128], p2 = pj[256], p3 = pj[384], p4 = pj[512];
            const float* vj = Vin  + ((size_t)j*128 + f)*3;
            const float* bjv = Vbin + ((size_t)j*128 + f)*3;
            float v0 = vj[0], v1 = vj[1], v2 = vj[2];
            float b0 = bjv[0], b1 = bjv[1], b2 = bjv[2];
            float w[5];
#pragma unroll
            for (int c = 0; c < 5; c++) {
                float s = breg[c];
#pragma unroll
                for (int k = 0; k < NRBF; k++)
                    s = fmaf(r[k], wreg[c][k], s);
                w[c] = s * ev;
            }
            float i0v = p0 * w[0];
            float i1v = p1 * w[1];
            float i2v = p2 * w[2];
            float i3v = p3 * w[3];
            float i4v = p4 * w[4];
            aH += i1v;
            aS += i3v;
            float ua0 = i2v*u0, ua1 = i2v*u1, ua2 = i2v*u2;
            aV0 += ua0 + i0v*v0;
            aV1 += ua1 + i0v*v1;
            aV2 += ua2 + i0v*v2;
            aB0 += ua0 + i4v*b0;
            aB1 += ua1 + i4v*b1;
            aB2 += ua2 + i4v*b2;
        }
        size_t hi = (size_t)i*128 + f;
        H[hi]    += aH;
        Sbar[hi] += aS;
        size_t vi = hi*3;
        Vout[vi+0]  = Vin[vi+0]  + aV0;
        Vout[vi+1]  = Vin[vi+1]  + aV1;
        Vout[vi+2]  = Vin[vi+2]  + aV2;
        Vbout[vi+0] = Vbin[vi+0] + aB0;
        Vbout[vi+1] = Vbin[vi+1] + aB1;
        Vbout[vi+2] = Vbin[vi+2] + aB2;
    }
}

// ---------------- u_v / v_v / v_norm (8 nodes/block, [d][f] smem, float4 LDS) --
__global__ void __launch_bounds__(128) upd_uv_kernel(
    const float* __restrict__ Vc, const float* __restrict__ U,
    const float* __restrict__ Wt,
    float* __restrict__ uv, float* __restrict__ vv, float* __restrict__ vn)
{
    __shared__ __align__(16) float sV[8][3][128];   // 12 KB
    int g = threadIdx.x;
    int n0 = blockIdx.x * 8;
#pragma unroll
    for (int n = 0; n < 8; n++) {
        const float* src = Vc + (size_t)(n0+n)*384;
#pragma unroll
        for (int r = 0; r < 3; r++) {
            int j = r*128 + g;          // j = f*3 + d
            sV[n][j % 3][j / 3] = src[j];
        }
    }
    __syncthreads();
    float aU[8][3] = {}, aV[8][3] = {};
    for (int f = 0; f < 128; f += 4) {
        float u0 = U[(f+0)*128 + g], u1 = U[(f+1)*128 + g];
        float u2 = U[(f+2)*128 + g], u3 = U[(f+3)*128 + g];
        float w0 = Wt[(f+0)*128 + g], w1 = Wt[(f+1)*128 + g];
        float w2 = Wt[(f+2)*128 + g], w3 = Wt[(f+3)*128 + g];
#pragma unroll
        for (int n = 0; n < 8; n++) {
#pragma unroll
            for (int d = 0; d < 3; d++) {
                float4 x = *(const float4*)&sV[n][d][f];
                float su = aU[n][d];
                su = fmaf(u0, x.x, su);
                su = fmaf(u1, x.y, su);
                su = fmaf(u2, x.z, su);
                su = fmaf(u3, x.w, su);
                aU[n][d] = su;
                float sw = aV[n][d];
                sw = fmaf(w0, x.x, sw);
                sw = fmaf(w1, x.y, sw);
                sw = fmaf(w2, x.z, sw);
                sw = fmaf(w3, x.w, sw);
                aV[n][d] = sw;
            }
        }
    }
#pragma unroll
    for (int n = 0; n < 8; n++) {
        int node = n0 + n;
        float nv = sqrtf(aV[n][0]*aV[n][0] + aV[n][1]*aV[n][1] +
                         aV[n][2]*aV[n][2] + 1e-15f);
        vn[(size_t)node*128 + g] = nv;
        size_t b = ((size_t)node*128 + g)*3;
        uv[b+0] = aU[n][0]; uv[b+1] = aU[n][1]; uv[b+2] = aU[n][2];
        vv[b+0] = aV[n][0]; vv[b+1] = aV[n][1]; vv[b+2] = aV[n][2];
    }
}

// ---------------- final gated update ----------------
__global__ void final_upd_kernel(float* __restrict__ H, float* __restrict__ V,
                                 const float* __restrict__ uv,
                                 const float* __restrict__ vv,
                                 const float* __restrict__ a)
{
    int idx = blockIdx.x*blockDim.x + threadIdx.x;
    if (idx >= NN*128) return;
    int n = idx >> 7, g = idx & 127;
    float a0 = a[(size_t)n*384 + g];
    float a1 = a[(size_t)n*384 + 128 + g];
    float a2 = a[(size_t)n*384 + 256 + g];
    size_t b = (size_t)idx*3;
    float u0 = uv[b], u1 = uv[b+1], u2 = uv[b+2];
    float dot = u0*vv[b] + u1*vv[b+1] + u2*vv[b+2];
    H[idx] += fmaf(a1, dot, a2);
    V[b+0] += a0*u0;
    V[b+1] += a0*u1;
    V[b+2] += a0*u2;
}

// ---------------- host ----------------
extern "C" void kernel_launch(void* const* d_in, const int* in_sizes, int n_in,
                              void* d_out, int out_size) {
    const float* xyz    = (const float*)d_in[0];
    const int*   nbr    = (const int*)  d_in[1];
    const float* Hin    = (const float*)d_in[3];
    const float* msg_W1 = (const float*)d_in[4];
    const float* msg_b1 = (const float*)d_in[5];
    const float* msg_W2 = (const float*)d_in[6];
    const float* msg_b2 = (const float*)d_in[7];
    const float* dist_W = (const float*)d_in[8];
    const float* dist_b = (const float*)d_in[9];
    const float* upd_U  = (const float*)d_in[10];
    const float* upd_Vw = (const float*)d_in[11];
    const float* upd_W1 = (const float*)d_in[12];
    const float* upd_b1 = (const float*)d_in[13];
    const float* upd_W2 = (const float*)d_in[14];
    const float* upd_b2 = (const float*)d_in[15];

    float* outH = (float*)d_out;

    float *Sbar, *V, *Valt, *Vb0, *Vb1, *phi, *tmp, *t2, *aBuf, *uv, *vv, *vn;
    int* cnt;
    cudaGetSymbolAddress((void**)&Sbar, g_Sbar);
    cudaGetSymbolAddress((void**)&V,    g_V);
    cudaGetSymbolAddress((void**)&Valt, g_Valt);
    cudaGetSymbolAddress((void**)&Vb0,  g_Vb0);
    cudaGetSymbolAddress((void**)&Vb1,  g_Vb1);
    cudaGetSymbolAddress((void**)&phi,  g_phi);
    cudaGetSymbolAddress((void**)&tmp,  g_tmp);
    cudaGetSymbolAddress((void**)&t2,   g_t2);
    cudaGetSymbolAddress((void**)&aBuf, g_a);
    cudaGetSymbolAddress((void**)&uv,   g_uv);
    cudaGetSymbolAddress((void**)&vv,   g_vv);
    cudaGetSymbolAddress((void**)&vn,   g_vn);
    cudaGetSymbolAddress((void**)&cnt,  g_cnt);

    float* outV = (out_size >= NN*FD + NN*FD*3) ? (outH + NN*FD) : Valt;

    // init via DMA (graph-capturable async memops)
    cudaMemsetAsync(cnt,  0, NN*sizeof(int));
    cudaMemsetAsync(Sbar, 0, (size_t)NN*FD*sizeof(float));
    cudaMemsetAsync(V,    0, (size_t)NN*FD*3*sizeof(float));
    cudaMemsetAsync(Vb0,  0, (size_t)NN*FD*3*sizeof(float));
    cudaMemcpyAsync(outH, Hin, (size_t)NN*FD*sizeof(float),
                    cudaMemcpyDeviceToDevice);

    count_kernel<<<(NE+255)/256, 256>>>(nbr);
    scan_kernel<<<1, 1024>>>();

    float* Vbufs[2] = {V,   outV};
    float* Bbufs[2] = {Vb0, Vb1};

    const int MT32 = (NN + 31) / 32;   // 313

    for (int l = 0; l < 3; l++) {
        const float* W1  = msg_W1 + (size_t)l*256*256;
        const float* b1  = msg_b1 + (size_t)l*256;
        const float* W2  = msg_W2 + (size_t)l*256*640;
        const float* b2  = msg_b2 + (size_t)l*640;
        const float* dWl = dist_W + (size_t)l*20*640;
        const float* dbl = dist_b + (size_t)l*640;
        const float* Ul  = upd_U  + (size_t)l*128*128;
        const float* Wtl = upd_Vw + (size_t)l*128*128;
        const float* uW1 = upd_W1 + (size_t)l*256*128;
        const float* ub1 = upd_b1 + (size_t)l*128;
        const float* uW2 = upd_W2 + (size_t)l*128*384;
        const float* ub2 = upd_b2 + (size_t)l*384;

        float* Vin   = Vbufs[l & 1];
        float* Vout_ = Vbufs[(l+1) & 1];
        float* Bin   = Bbufs[l & 1];
        float* Bout  = Bbufs[(l+1) & 1];

        // tmp = silu([H|Sbar] @ W1 + b1)   [10000,256]  grid=(4,313)
        gemm_tc<32,64,4,4,6,1><<<dim3(256/64, MT32), 128>>>(
            outH, 128, Sbar, 128, 128, W1, b1, tmp, NN, 256, 256);
        if (l == 0) {
            fill_kernel<<<(NE+255)/256, 256>>>(nbr);
            sort_kernel<<<(NN+127)/128, 128>>>();
            edge_geom_kernel<<<(NE+127)/128, 128>>>(xyz, nbr);
        }
        // phi = tmp @ W2 + b2              [10000,640]  grid=(10,313)
        gemm_tc<32,64,4,4,6,0><<<dim3(640/64, MT32), 128>>>(
            tmp, 256, tmp, 256, 256, W2, b2, phi, NN, 640, 256);
        // message aggregation (4 nodes/block -> 2500 blocks)
        agg_kernel<<<(NN+3)/4, 128>>>(phi, dWl, dbl, nbr,
                                      Vin, Vout_, Bin, Bout, outH, Sbar);
        // u_v, v_v, v_norm (8 nodes/block)
        upd_uv_kernel<<<NN/8, 128>>>(Vout_, Ul, Wtl, uv, vv, vn);
        // t2 = silu([H|v_norm] @ uW1 + ub1)  [10000,128]  grid=(2,313)
        gemm_tc<32,64,4,4,6,1><<<dim3(128/64, MT32), 128>>>(
            outH, 128, vn, 128, 128, uW1, ub1, t2, NN, 128, 256);
        // a = t2 @ uW2 + ub2               [10000,384]  grid=(6,313)
        gemm_tc<32,64,4,4,6,0><<<dim3(384/64, MT32), 128>>>(
            t2, 128, t2, 128, 128, uW2, ub2, aBuf, NN, 384, 128);
        // H += a1*dot + a2 ; V += a0*u_v
        final_upd_kernel<<<(NN*128+255)/256, 256>>>(outH, Vout_, uv, vv, aBuf);
    }
}

// round 17
// speedup vs baseline: 1.0601x; 1.0294x over previous
#include <cuda_runtime.h>
#include <math.h>

#define NN 10000
#define NE 160000
#define FD 128
#define NRBF 20
#define PI_F 3.14159265358979f

// ---------------- device scratch (static, no runtime alloc) ----------------
__device__ float g_Sbar[NN*FD];
__device__ float g_V[NN*FD*3];
__device__ float g_Valt[NN*FD*3];
__device__ float g_Vb0[NN*FD*3];
__device__ float g_Vb1[NN*FD*3];
__device__ float g_phi[NN*640];
__device__ float g_tmp[NN*256];
__device__ float g_t2[NN*FD];
__device__ float g_a[NN*384];
__device__ float g_uv[NN*FD*3];
__device__ float g_vv[NN*FD*3];
__device__ float g_vn[NN*FD];
__device__ float4 g_ue[NE];          // unit.xyz + env in one float4
__device__ float g_rbf[NE*NRBF];
__device__ int   g_cnt[NN];
__device__ int   g_off[NN+1];
__device__ int   g_cur[NN];
__device__ int   g_perm[NE];

// ---------------- CSR build ----------------
__global__ void count_kernel(const int* __restrict__ nbr) {
    int e = blockIdx.x*blockDim.x + threadIdx.x;
    if (e < NE) atomicAdd(&g_cnt[nbr[2*e]], 1);
}

__global__ void scan_kernel() {
    __shared__ int s[1024];
    int t = threadIdx.x;
    const int CH = (NN + 1023) / 1024;
    int base = t*CH;
    int local[CH];
    int sum = 0;
#pragma unroll
    for (int i = 0; i < CH; i++) {
        int v = (base+i < NN) ? g_cnt[base+i] : 0;
        local[i] = v; sum += v;
    }
    s[t] = sum;
    __syncthreads();
    for (int d = 1; d < 1024; d <<= 1) {
        int v = (t >= d) ? s[t-d] : 0;
        __syncthreads();
        s[t] += v;
        __syncthreads();
    }
    int prefix = (t == 0) ? 0 : s[t-1];
#pragma unroll
    for (int i = 0; i < CH; i++) {
        if (base+i < NN) {
            g_off[base+i] = prefix;
            g_cur[base+i] = prefix;
            prefix += local[i];
        }
    }
    if (t == 1023) g_off[NN] = s[1023];
}

__global__ void fill_kernel(const int* __restrict__ nbr) {
    int e = blockIdx.x*blockDim.x + threadIdx.x;
    if (e < NE) {
        int sN = nbr[2*e];
        int p = atomicAdd(&g_cur[sN], 1);
        g_perm[p] = e;
    }
}

__global__ void sort_kernel() {
    int i = blockIdx.x*blockDim.x + threadIdx.x;
    if (i >= NN) return;
    int a = g_off[i], b = g_off[i+1];
    for (int x = a+1; x < b; x++) {
        int v = g_perm[x];
        int y = x-1;
        while (y >= a && g_perm[y] > v) { g_perm[y+1] = g_perm[y]; y--; }
        g_perm[y+1] = v;
    }
}

// ---------------- edge geometry ----------------
__global__ void edge_geom_kernel(const float* __restrict__ xyz,
                                 const int* __restrict__ nbr) {
    int e = blockIdx.x*blockDim.x + threadIdx.x;
    if (e >= NE) return;
    int s = nbr[2*e], d = nbr[2*e+1];
    float dx = xyz[3*d+0] - xyz[3*s+0];
    float dy = xyz[3*d+1] - xyz[3*s+1];
    float dz = xyz[3*d+2] - xyz[3*s+2];
    float dist = sqrtf(dx*dx + dy*dy + dz*dz);
    float inv = 1.0f / dist;
    float4 ue;
    ue.x = dx*inv; ue.y = dy*inv; ue.z = dz*inv;
    ue.w = (dist < 5.0f) ? 0.5f*(__cosf(PI_F*dist*0.2f) + 1.0f) : 0.0f;
    g_ue[e] = ue;
    float base = PI_F*0.2f*dist;
#pragma unroll
    for (int k = 0; k < NRBF; k++)
        g_rbf[e*NRBF+k] = __sinf((float)(k+1)*base) * inv;
}

// ---------------- general fused GEMM (R14 config, BK=16) ----------------
template<int BM, int BN, int TM, int TN, int OCC, int ACT>
__global__ void __launch_bounds__((BM/TM)*(BN/TN), OCC) gemm_tc(
    const float* __restrict__ A0, int lda0,
    const float* __restrict__ A1, int lda1, int K0,
    const float* __restrict__ W, const float* __restrict__ bias,
    float* __restrict__ C, int M, int N, int K)
{
    const int BK = 16;
    const int NT  = (BM/TM)*(BN/TN);
    const int ASL = BM*(BK/4)/NT;
    const int BSL = BN*(BK/4)/NT;
    static_assert(ASL >= 1 && BSL >= 1, "tile/thread mismatch");
    __shared__ __align__(16) float As[2][BK][BM];
    __shared__ __align__(16) float Bs[2][BK][BN];

    int t  = threadIdx.x;
    int bm = blockIdx.y*BM, bn = blockIdx.x*BN;
    int tx = t % (BN/TN);
    int ty = t / (BN/TN);

    float acc[TM][TN];
#pragma unroll
    for (int i = 0; i < TM; i++)
#pragma unroll
        for (int j = 0; j < TN; j++) acc[i][j] = 0.0f;

    float4 ra[ASL];
    float4 rb[BSL];

#define LOAD_AB(k0)                                                           \
    {   _Pragma("unroll")                                                     \
        for (int i = 0; i < ASL; i++) {                                       \
            int idx = t + i*NT;                                               \
            int am = idx % BM, kc = idx / BM;                                 \
            int gm = bm + am, gk = (k0) + kc*4;                               \
            if (gm < M) {                                                     \
                const float* p = (gk < K0) ? (A0 + (size_t)gm*lda0 + gk)      \
                                           : (A1 + (size_t)gm*lda1 + (gk-K0));\
                ra[i] = *(const float4*)p;                                    \
            } else ra[i] = make_float4(0,0,0,0);                              \
        }                                                                     \
        _Pragma("unroll")                                                     \
        for (int i = 0; i < BSL; i++) {                                       \
            int idx = t + i*NT;                                               \
            int n4 = (idx % (BN/4))*4, k = idx / (BN/4);                      \
            rb[i] = *(const float4*)(W + (size_t)((k0)+k)*N + bn + n4);       \
        }                                                                     \
    }
#define STORE_AB(st)                                                          \
    {   _Pragma("unroll")                                                     \
        for (int i = 0; i < ASL; i++) {                                       \
            int idx = t + i*NT;                                               \
            int am = idx % BM, kc = idx / BM;                                 \
            As[st][kc*4+0][am] = ra[i].x;                                     \
            As[st][kc*4+1][am] = ra[i].y;                                     \
            As[st][kc*4+2][am] = ra[i].z;                                     \
            As[st][kc*4+3][am] = ra[i].w;                                     \
        }                                                                     \
        _Pragma("unroll")                                                     \
        for (int i = 0; i < BSL; i++) {                                       \
            int idx = t + i*NT;                                               \
            int n4 = (idx % (BN/4))*4, k = idx / (BN/4);                      \
            *(float4*)&Bs[st][k][n4] = rb[i];                                 \
        }                                                                     \
    }
#define COMPUTE(st)                                                           \
    {   _Pragma("unroll")                                                     \
        for (int kk = 0; kk < BK; kk++) {                                     \
            float av[TM], bv[TN];                                             \
            _Pragma("unroll")                                                 \
            for (int i = 0; i < TM; i += 4)                                   \
                *(float4*)&av[i] = *(const float4*)&As[st][kk][ty*TM + i];    \
            _Pragma("unroll")                                                 \
            for (int j = 0; j < TN; j += 4)                                   \
                *(float4*)&bv[j] = *(const float4*)&Bs[st][kk][tx*TN + j];    \
            _Pragma("unroll")                                                 \
            for (int i = 0; i < TM; i++)                                      \
            _Pragma("unroll")                                                 \
            for (int j = 0; j < TN; j++)                                      \
                acc[i][j] = fmaf(av[i], bv[j], acc[i][j]);                    \
        }                                                                     \
    }

    LOAD_AB(0);
    STORE_AB(0);
    __syncthreads();

    int st = 0;
    for (int k0 = BK; k0 < K; k0 += BK) {
        LOAD_AB(k0);
        COMPUTE(st);
        STORE_AB(st^1);
        __syncthreads();
        st ^= 1;
    }
    COMPUTE(st);

    float bj[TN];
#pragma unroll
    for (int j = 0; j < TN; j += 4)
        *(float4*)&bj[j] = *(const float4*)(bias + bn + tx*TN + j);
#pragma unroll
    for (int i = 0; i < TM; i++) {
        int gm = bm + ty*TM + i;
        if (gm >= M) continue;
        float* cp = C + (size_t)gm*N + bn + tx*TN;
#pragma unroll
        for (int j = 0; j < TN; j += 4) {
            float4 v;
            v.x = acc[i][j+0] + bj[j+0];
            v.y = acc[i][j+1] + bj[j+1];
            v.z = acc[i][j+2] + bj[j+2];
            v.w = acc[i][j+3] + bj[j+3];
            if (ACT) {
                v.x = v.x / (1.0f + __expf(-v.x));
                v.y = v.y / (1.0f + __expf(-v.y));
                v.z = v.z / (1.0f + __expf(-v.z));
                v.w = v.w / (1.0f + __expf(-v.w));
            }
            *(float4*)(cp + j) = v;
        }
    }
#undef LOAD_AB
#undef STORE_AB
#undef COMPUTE
}

// ---------------- edge aggregation (R2 compute, 2 nodes/block, packed ue) ----
__global__ void __launch_bounds__(128, 3) agg_kernel(
    const float* __restrict__ phi, const float* __restrict__ dW,
    const float* __restrict__ db, const int* __restrict__ nbr,
    const float* __restrict__ Vin, float* __restrict__ Vout,
    const float* __restrict__ Vbin, float* __restrict__ Vbout,
    float* __restrict__ H, float* __restrict__ Sbar)
{
    const int f = threadIdx.x;
    float wreg[5][NRBF];
    float breg[5];
#pragma unroll
    for (int c = 0; c < 5; c++) {
        breg[c] = db[c*128 + f];
#pragma unroll
        for (int k = 0; k < NRBF; k++)
            wreg[c][k] = dW[k*640 + c*128 + f];
    }
    int i0 = blockIdx.x * 2;
    for (int ii = 0; ii < 2; ii++) {
        int i = i0 + ii;
        if (i >= NN) return;
        float aH = 0.f, aS = 0.f;
        float aV0 = 0.f, aV1 = 0.f, aV2 = 0.f;
        float aB0 = 0.f, aB1 = 0.f, aB2 = 0.f;
        int e0 = g_off[i], e1 = g_off[i+1];
        int e_n = 0, j_n = 0;
        if (e0 < e1) { e_n = g_perm[e0]; j_n = nbr[2*e_n+1]; }
        for (int p = e0; p < e1; p++) {
            int e = e_n, j = j_n;
            if (p+1 < e1) { e_n = g_perm[p+1]; j_n = nbr[2*e_n+1]; }
            float4 ue = g_ue[e];
            float u0 = ue.x, u1 = ue.y, u2 = ue.z, ev = ue.w;
            const float4* rq = (const float4*)(g_rbf + e*NRBF);
            float4 q0 = rq[0], q1 = rq[1], q2 = rq[2], q3 = rq[3], q4 = rq[4];
            float r[NRBF] = {q0.x,q0.y,q0.z,q0.w, q1.x,q1.y,q1.z,q1.w,
                             q2.x,q2.y,q2.z,q2.w, q3.x,q3.y,q3.z,q3.w,
                             q4.x,q4.y,q4.z,q4.w};
            const float* pj = phi + (size_t)j*640 + f;
            float p0 = pj[0], p1 = pj[128], p2 = pj[256], p3 = pj[384], p4 = pj[512];
            const float* vj = Vin  + ((size_t)j*128 + f)*3;
            const float* bjv = Vbin + ((size_t)j*128 + f)*3;
            float v0 = vj[0], v1 = vj[1], v2 = vj[2];
            float b0 = bjv[0], b1 = bjv[1], b2 = bjv[2];
            float w[5];
#pragma unroll
            for (int c = 0; c < 5; c++) {
                float s = breg[c];
#pragma unroll
                for (int k = 0; k < NRBF; k++)
                    s = fmaf(r[k], wreg[c][k], s);
                w[c] = s * ev;
            }
            float i0v = p0 * w[0];
            float i1v = p1 * w[1];
            float i2v = p2 * w[2];
            float i3v = p3 * w[3];
            float i4v = p4 * w[4];
            aH += i1v;
            aS += i3v;
            float ua0 = i2v*u0, ua1 = i2v*u1, ua2 = i2v*u2;
            aV0 += ua0 + i0v*v0;
            aV1 += ua1 + i0v*v1;
            aV2 += ua2 + i0v*v2;
            aB0 += ua0 + i4v*b0;
            aB1 += ua1 + i4v*b1;
            aB2 += ua2 + i4v*b2;
        }
        size_t hi = (size_t)i*128 + f;
        H[hi]    += aH;
        Sbar[hi] += aS;
        size_t vi = hi*3;
        Vout[vi+0]  = Vin[vi+0]  + aV0;
        Vout[vi+1]  = Vin[vi+1]  + aV1;
        Vout[vi+2]  = Vin[vi+2]  + aV2;
        Vbout[vi+0] = Vbin[vi+0] + aB0;
        Vbout[vi+1] = Vbin[vi+1] + aB1;
        Vbout[vi+2] = Vbin[vi+2] + aB2;
    }
}

// ---------------- u_v / v_v / v_norm (8 nodes/block, [d][f] smem, float4 LDS) --
__global__ void __launch_bounds__(128) upd_uv_kernel(
    const float* __restrict__ Vc, const float* __restrict__ U,
    const float* __restrict__ Wt,
    float* __restrict__ uv, float* __restrict__ vv, float* __restrict__ vn)
{
    __shared__ __align__(16) float sV[8][3][128];   // 12 KB
    int g = threadIdx.x;
    int n0 = blockIdx.x * 8;
#pragma unroll
    for (int n = 0; n < 8; n++) {
        const float* src = Vc + (size_t)(n0+n)*384;
#pragma unroll
        for (int r = 0; r < 3; r++) {
            int j = r*128 + g;          // j = f*3 + d
            sV[n][j % 3][j / 3] = src[j];
        }
    }
    __syncthreads();
    float aU[8][3] = {}, aV[8][3] = {};
    for (int f = 0; f < 128; f += 4) {
        float u0 = U[(f+0)*128 + g], u1 = U[(f+1)*128 + g];
        float u2 = U[(f+2)*128 + g], u3 = U[(f+3)*128 + g];
        float w0 = Wt[(f+0)*128 + g], w1 = Wt[(f+1)*128 + g];
        float w2 = Wt[(f+2)*128 + g], w3 = Wt[(f+3)*128 + g];
#pragma unroll
        for (int n = 0; n < 8; n++) {
#pragma unroll
            for (int d = 0; d < 3; d++) {
                float4 x = *(const float4*)&sV[n][d][f];
                float su = aU[n][d];
                su = fmaf(u0, x.x, su);
                su = fmaf(u1, x.y, su);
                su = fmaf(u2, x.z, su);
                su = fmaf(u3, x.w, su);
                aU[n][d] = su;
                float sw = aV[n][d];
                sw = fmaf(w0, x.x, sw);
                sw = fmaf(w1, x.y, sw);
                sw = fmaf(w2, x.z, sw);
                sw = fmaf(w3, x.w, sw);
                aV[n][d] = sw;
            }
        }
    }
#pragma unroll
    for (int n = 0; n < 8; n++) {
        int node = n0 + n;
        float nv = sqrtf(aV[n][0]*aV[n][0] + aV[n][1]*aV[n][1] +
                         aV[n][2]*aV[n][2] + 1e-15f);
        vn[(size_t)node*128 + g] = nv;
        size_t b = ((size_t)node*128 + g)*3;
        uv[b+0] = aU[n][0]; uv[b+1] = aU[n][1]; uv[b+2] = aU[n][2];
        vv[b+0] = aV[n][0]; vv[b+1] = aV[n][1]; vv[b+2] = aV[n][2];
    }
}

// ---------------- final gated update ----------------
__global__ void final_upd_kernel(float* __restrict__ H, float* __restrict__ V,
                                 const float* __restrict__ uv,
                                 const float* __restrict__ vv,
                                 const float* __restrict__ a)
{
    int idx = blockIdx.x*blockDim.x + threadIdx.x;
    if (idx >= NN*128) return;
    int n = idx >> 7, g = idx & 127;
    float a0 = a[(size_t)n*384 + g];
    float a1 = a[(size_t)n*384 + 128 + g];
    float a2 = a[(size_t)n*384 + 256 + g];
    size_t b = (size_t)idx*3;
    float u0 = uv[b], u1 = uv[b+1], u2 = uv[b+2];
    float dot = u0*vv[b] + u1*vv[b+1] + u2*vv[b+2];
    H[idx] += fmaf(a1, dot, a2);
    V[b+0] += a0*u0;
    V[b+1] += a0*u1;
    V[b+2] += a0*u2;
}

// ---------------- host ----------------
extern "C" void kernel_launch(void* const* d_in, const int* in_sizes, int n_in,
                              void* d_out, int out_size) {
    const float* xyz    = (const float*)d_in[0];
    const int*   nbr    = (const int*)  d_in[1];
    const float* Hin    = (const float*)d_in[3];
    const float* msg_W1 = (const float*)d_in[4];
    const float* msg_b1 = (const float*)d_in[5];
    const float* msg_W2 = (const float*)d_in[6];
    const float* msg_b2 = (const float*)d_in[7];
    const float* dist_W = (const float*)d_in[8];
    const float* dist_b = (const float*)d_in[9];
    const float* upd_U  = (const float*)d_in[10];
    const float* upd_Vw = (const float*)d_in[11];
    const float* upd_W1 = (const float*)d_in[12];
    const float* upd_b1 = (const float*)d_in[13];
    const float* upd_W2 = (const float*)d_in[14];
    const float* upd_b2 = (const float*)d_in[15];

    float* outH = (float*)d_out;

    float *Sbar, *V, *Valt, *Vb0, *Vb1, *phi, *tmp, *t2, *aBuf, *uv, *vv, *vn;
    int* cnt;
    cudaGetSymbolAddress((void**)&Sbar, g_Sbar);
    cudaGetSymbolAddress((void**)&V,    g_V);
    cudaGetSymbolAddress((void**)&Valt, g_Valt);
    cudaGetSymbolAddress((void**)&Vb0,  g_Vb0);
    cudaGetSymbolAddress((void**)&Vb1,  g_Vb1);
    cudaGetSymbolAddress((void**)&phi,  g_phi);
    cudaGetSymbolAddress((void**)&tmp,  g_tmp);
    cudaGetSymbolAddress((void**)&t2,   g_t2);
    cudaGetSymbolAddress((void**)&aBuf, g_a);
    cudaGetSymbolAddress((void**)&uv,   g_uv);
    cudaGetSymbolAddress((void**)&vv,   g_vv);
    cudaGetSymbolAddress((void**)&vn,   g_vn);
    cudaGetSymbolAddress((void**)&cnt,  g_cnt);

    float* outV = (out_size >= NN*FD + NN*FD*3) ? (outH + NN*FD) : Valt;

    // init via DMA (graph-capturable async memops)
    cudaMemsetAsync(cnt,  0, NN*sizeof(int));
    cudaMemsetAsync(Sbar, 0, (size_t)NN*FD*sizeof(float));
    cudaMemsetAsync(V,    0, (size_t)NN*FD*3*sizeof(float));
    cudaMemsetAsync(Vb0,  0, (size_t)NN*FD*3*sizeof(float));
    cudaMemcpyAsync(outH, Hin, (size_t)NN*FD*sizeof(float),
                    cudaMemcpyDeviceToDevice);

    count_kernel<<<(NE+255)/256, 256>>>(nbr);
    scan_kernel<<<1, 1024>>>();

    float* Vbufs[2] = {V,   outV};
    float* Bbufs[2] = {Vb0, Vb1};

    const int MT32 = (NN + 31) / 32;   // 313

    for (int l = 0; l < 3; l++) {
        const float* W1  = msg_W1 + (size_t)l*256*256;
        const float* b1  = msg_b1 + (size_t)l*256;
        const float* W2  = msg_W2 + (size_t)l*256*640;
        const float* b2  = msg_b2 + (size_t)l*640;
        const float* dWl = dist_W + (size_t)l*20*640;
        const float* dbl = dist_b + (size_t)l*640;
        const float* Ul  = upd_U  + (size_t)l*128*128;
        const float* Wtl = upd_Vw + (size_t)l*128*128;
        const float* uW1 = upd_W1 + (size_t)l*256*128;
        const float* ub1 = upd_b1 + (size_t)l*128;
        const float* uW2 = upd_W2 + (size_t)l*128*384;
        const float* ub2 = upd_b2 + (size_t)l*384;

        float* Vin   = Vbufs[l & 1];
        float* Vout_ = Vbufs[(l+1) & 1];
        float* Bin   = Bbufs[l & 1];
        float* Bout  = Bbufs[(l+1) & 1];

        // tmp = silu([H|Sbar] @ W1 + b1)   [10000,256]  grid=(4,313)
        gemm_tc<32,64,4,4,6,1><<<dim3(256/64, MT32), 128>>>(
            outH, 128, Sbar, 128, 128, W1, b1, tmp, NN, 256, 256);
        if (l == 0) {
            fill_kernel<<<(NE+255)/256, 256>>>(nbr);
            sort_kernel<<<(NN+127)/128, 128>>>();
            edge_geom_kernel<<<(NE+127)/128, 128>>>(xyz, nbr);
        }
        // phi = tmp @ W2 + b2              [10000,640]  grid=(10,313)
        gemm_tc<32,64,4,4,6,0><<<dim3(640/64, MT32), 128>>>(
            tmp, 256, tmp, 256, 256, W2, b2, phi, NN, 640, 256);
        // message aggregation (2 nodes/block -> 5000 blocks)
        agg_kernel<<<(NN+1)/2, 128>>>(phi, dWl, dbl, nbr,
                                      Vin, Vout_, Bin, Bout, outH, Sbar);
        // u_v, v_v, v_norm (8 nodes/block)
        upd_uv_kernel<<<NN/8, 128>>>(Vout_, Ul, Wtl, uv, vv, vn);
        // t2 = silu([H|v_norm] @ uW1 + ub1)  [10000,128]  grid=(2,313)
        gemm_tc<32,64,4,4,6,1><<<dim3(128/64, MT32), 128>>>(
            outH, 128, vn, 128, 128, uW1, ub1, t2, NN, 128, 256);
        // a = t2 @ uW2 + ub2               [10000,384]  grid=(6,313)
        gemm_tc<32,64,4,4,6,0><<<dim3(384/64, MT32), 128>>>(
            t2, 128, t2, 128, 128, uW2, ub2, aBuf, NN, 384, 128);
        // H += a1*dot + a2 ; V += a0*u_v
        final_upd_kernel<<<(NN*128+255)/256, 256>>>(outH, Vout_, uv, vv, aBuf);
    }
}